// round 2
// baseline (speedup 1.0000x reference)
#include <cuda_runtime.h>
#include <cuda_bf16.h>
#include <math.h>

// ArcFace-style margin softmax cross-entropy loss.
//   B = 2048 rows, C = 50000 classes (derived at runtime from in_sizes).
//   loss = mean_b [ logsumexp_c(logits[b,c]) - logits[b, label_b] ]
// with logits = clip(cos,-1+eps,1-eps)*64, and label column replaced by
// (ct*cos(m) - sqrt(1-ct^2)*sin(m))*64.
//
// Single pass over cos_theta using fixed-shift logsumexp (shift = 64 = max
// possible logit): lse = 64 + log(sum exp(logit - 64)). All exponents <= 0,
// no overflow; underflow is negligible at 1e-3 rel tolerance.

#define EPS_CLIP 1e-7f
#define SCALE 64.0f

static __device__ float g_row_loss[4096];  // scratch for per-row losses (B <= 4096)

__device__ __forceinline__ float clipf(float x) {
    return fminf(fmaxf(x, -1.0f + EPS_CLIP), 1.0f - EPS_CLIP);
}

// exp(logit - 64) where logit = clip(x)*64, via fast exp
__device__ __forceinline__ float term(float x) {
    return __expf(fmaf(clipf(x), SCALE, -SCALE));
}

__global__ void __launch_bounds__(256) margin_row_kernel(
    const float* __restrict__ cos_theta,
    const int* __restrict__ labels,
    const float* __restrict__ margins,
    int C)
{
    const int row = blockIdx.x;
    const int tid = threadIdx.x;
    const size_t row_off = (size_t)row * (size_t)C;
    const float4* rp = reinterpret_cast<const float4*>(cos_theta + row_off);
    const int n4 = C >> 2;

    float acc = 0.0f;
    // strided float4 loads; fixed per-thread order -> deterministic
    for (int i = tid; i < n4; i += 256) {
        float4 v = rp[i];
        acc += term(v.x);
        acc += term(v.y);
        acc += term(v.z);
        acc += term(v.w);
    }
    // tail (C % 4) — C=50000 divisible by 4, but keep general
    for (int i = (n4 << 2) + tid; i < C; i += 256) {
        acc += term(cos_theta[row_off + i]);
    }

    __shared__ float sdata[256];
    sdata[tid] = acc;
    __syncthreads();
    // deterministic tree reduction
    #pragma unroll
    for (int s = 128; s > 0; s >>= 1) {
        if (tid < s) sdata[tid] += sdata[tid + s];
        __syncthreads();
    }

    if (tid == 0) {
        int lab = labels[row];
        float cl = clipf(cos_theta[row_off + (size_t)lab]);
        float m = margins[lab];
        float cm = cosf(m);
        float sm = sinf(m);
        float sin_l = sqrtf(fmaxf(1.0f - cl * cl, 0.0f));
        float target = cl * cm - sin_l * sm;          // cos(theta + m)
        float target_logit = target * SCALE;

        // replace label column contribution in the sum
        float sum = sdata[0]
                  + __expf(target_logit - SCALE)
                  - __expf(fmaf(cl, SCALE, -SCALE));

        float lse = SCALE + logf(sum);
        g_row_loss[row] = lse - target_logit;
    }
}

__global__ void __launch_bounds__(1024) final_reduce_kernel(float* __restrict__ out, int B)
{
    const int tid = threadIdx.x;
    float acc = 0.0f;
    for (int i = tid; i < B; i += 1024) acc += g_row_loss[i];

    __shared__ float sdata[1024];
    sdata[tid] = acc;
    __syncthreads();
    #pragma unroll
    for (int s = 512; s > 0; s >>= 1) {
        if (tid < s) sdata[tid] += sdata[tid + s];
        __syncthreads();
    }
    if (tid == 0) out[0] = sdata[0] / (float)B;
}

extern "C" void kernel_launch(void* const* d_in, const int* in_sizes, int n_in,
                              void* d_out, int out_size)
{
    const float* cos_theta = (const float*)d_in[0];
    const int*   labels    = (const int*)d_in[1];
    const float* margins   = (const float*)d_in[2];
    float* out = (float*)d_out;

    const int B = in_sizes[1];
    const int C = in_sizes[0] / B;

    margin_row_kernel<<<B, 256>>>(cos_theta, labels, margins, C);
    final_reduce_kernel<<<1, 1024>>>(out, B);
}